// round 16
// baseline (speedup 1.0000x reference)
#include <cuda_runtime.h>
#include <cuda_bf16.h>
#include <math.h>

#define T_SAMPLES 8388608
#define NFRAMES   16381
#define NBINS     84
#define FBINS     1025
#define FFTLEN    2048
#define HOP       512

typedef unsigned long long ull;

// ---- product matrix P[192][4096] = [kr;ki] @ [wcos | wsin], two K-half partials
__device__ float g_P0[192 * 4096];
__device__ float g_P1[192 * 4096];

// ---- bf16 split weights, padded MMA tiles: [32 kc][192 m][72 k] ----
#define WELEMS (32 * 192 * 72)
__device__ __nv_bfloat16 d_Whi[WELEMS];
__device__ __nv_bfloat16 d_Wlo[WELEMS];

// ======================= helpers =======================
__device__ __forceinline__ unsigned smem_u32(const void* p) {
    unsigned a;
    asm("{ .reg .u64 t; cvta.to.shared.u64 t, %1; cvt.u32.u64 %0, t; }"
        : "=r"(a) : "l"(p));
    return a;
}
#define CPA(dst, src) \
    asm volatile("cp.async.cg.shared.global [%0], [%1], 16;" :: "r"(dst), "l"(src))
#define CPA_Z(dst, src, nb) \
    asm volatile("cp.async.cg.shared.global [%0], [%1], 16, %2;" \
                 :: "r"(dst), "l"(src), "r"(nb))
#define CPA4_Z(dst, src, nb) \
    asm volatile("cp.async.ca.shared.global [%0], [%1], 4, %2;" \
                 :: "r"(dst), "l"(src), "r"(nb))
#define CPCOMMIT() asm volatile("cp.async.commit_group;" ::: "memory")
#define CPWAIT1()  asm volatile("cp.async.wait_group 1;" ::: "memory")

#define LDSM4(r, a) \
    asm volatile("ldmatrix.sync.aligned.m8n8.x4.shared.b16 {%0,%1,%2,%3}, [%4];" \
        : "=r"((r)[0]), "=r"((r)[1]), "=r"((r)[2]), "=r"((r)[3]) : "r"(a))
#define LDSM4T(r, a) \
    asm volatile("ldmatrix.sync.aligned.m8n8.x4.trans.shared.b16 {%0,%1,%2,%3}, [%4];" \
        : "=r"((r)[0]), "=r"((r)[1]), "=r"((r)[2]), "=r"((r)[3]) : "r"(a))

__device__ __forceinline__ void mma16816(float* c, const unsigned* a,
                                         unsigned b0, unsigned b1) {
    asm volatile(
        "mma.sync.aligned.m16n8k16.row.col.f32.bf16.bf16.f32 "
        "{%0,%1,%2,%3}, {%4,%5,%6,%7}, {%8,%9}, {%0,%1,%2,%3};"
        : "+f"(c[0]), "+f"(c[1]), "+f"(c[2]), "+f"(c[3])
        : "r"(a[0]), "r"(a[1]), "r"(a[2]), "r"(a[3]), "r"(b0), "r"(b1));
}

__device__ __forceinline__ void bsplit2(float v0, float v1,
                                        unsigned& h, unsigned& l) {
    __nv_bfloat162 hb = __float22bfloat162_rn(make_float2(v0, v1));
    const float2 hf = __bfloat1622float2(hb);
    __nv_bfloat162 lb = __float22bfloat162_rn(make_float2(v0 - hf.x, v1 - hf.y));
    h = *(unsigned*)&hb;
    l = *(unsigned*)&lb;
}

// ---------------------------------------------------------------------------
// Precompute GEMM: P[192,4096] = [kr(0-83); ki(96-179)] @ [wcos | wsin].
// Split-bf16 3-combo HMMA, cp.async double-buffered fp32 staging +
// in-smem convert. A staged with 4B cp.async (kr/ki rows are only 4B-aligned);
// X staged with 16B cp.async (wcos/wsin rows 16B-aligned).
// Grid (64 n-tiles, 2 K-halves).
// ---------------------------------------------------------------------------
#define PAST 144                    // bf16 tile row stride bytes (72 bf16)
#define PAH  0
#define PAL  (192 * 144)            // 27648
#define PXH  (2 * 192 * 144)        // 55296
#define PXL  (PXH + 64 * 144)       // 64512
#define PG_TILES (PXL + 64 * 144)   // 73728
#define PG_FST   272                // fp32 row stride bytes (68 floats)
#define PG_AFB   (192 * PG_FST)     // 52224
#define PG_XFB   (64 * PG_FST)      // 17408
#define PG_STG   (PG_AFB + PG_XFB)  // 69632
#define SMEM_PG  (PG_TILES + 2 * PG_STG)  // 212992

__global__ void __launch_bounds__(256, 1) cqt_pgemm(const float* __restrict__ wcos,
                                                    const float* __restrict__ wsin,
                                                    const float* __restrict__ kr,
                                                    const float* __restrict__ ki) {
    extern __shared__ __align__(128) char psm[];
    const unsigned sb = smem_u32(psm);
    const int tid  = threadIdx.x;
    const int lane = tid & 31;
    const int wid  = tid >> 5;
    const int ms   = wid >> 1;        // 0..3 M-stripe (48 rows)
    const int nh   = wid & 1;         // 0..1 N-half (32 cols)
    const int n0   = blockIdx.x * 64;
    const int half = blockIdx.y;
    const float* xsrc = (n0 < 2048) ? (wcos + n0) : (wsin + (n0 - 2048));
    const int nchunks = half ? 9 : 8;
    const int b0base  = half * 512;

    float acc[3][4][4];
    #pragma unroll
    for (int t = 0; t < 3; t++)
        #pragma unroll
        for (int nn = 0; nn < 4; nn++)
            #pragma unroll
            for (int j = 0; j < 4; j++) acc[t][nn][j] = 0.f;

    auto stage = [&](int c, int b) {
        const int b0 = b0base + c * 64;
        const unsigned abuf = sb + PG_TILES + b * PG_STG;
        const unsigned xbuf = abuf + PG_AFB;
        // A (kr rows 0-83, ki rows 96-179): 4B cp.async, per-element predicate.
        for (int i = tid; i < 192 * 64; i += 256) {
            const int m   = i >> 6;
            const int col = i & 63;
            const int bb  = b0 + col;
            const int bc  = min(bb, FBINS - 1);
            const float* src;
            int nb = 0;
            if (m < NBINS) {
                src = kr + (size_t)m * FBINS + bc;
                nb = (bb < FBINS) ? 4 : 0;
            } else if (m >= 96 && m < 96 + NBINS) {
                src = ki + (size_t)(m - 96) * FBINS + bc;
                nb = (bb < FBINS) ? 4 : 0;
            } else {
                src = kr;
            }
            CPA4_Z(abuf + m * PG_FST + col * 4, src, nb);
        }
        // X (wcos/wsin): 64 b-rows x 16 segs fp32, 16B-aligned.
        for (int i = tid; i < 1024; i += 256) {
            const int bb  = i >> 4;
            const int seg = i & 15;
            const int b_  = b0 + bb;
            const int bc  = min(b_, FBINS - 1);
            const float* src = xsrc + (size_t)bc * FFTLEN + seg * 4;
            const int nb = (b_ < FBINS) ? 16 : 0;
            CPA_Z(xbuf + bb * PG_FST + seg * 16, src, nb);
        }
        CPCOMMIT();
    };

    stage(0, 0);
    stage(1, 1);

    for (int c = 0; c < nchunks; c++) {
        const int b = c & 1;
        CPWAIT1();
        __syncthreads();

        // ---- convert fp32 -> bf16 hi/lo tiles (72-col padded) ----
        {
            const float* afp = (const float*)(psm + PG_TILES + b * PG_STG);
            const float* xfp = (const float*)(psm + PG_TILES + b * PG_STG + PG_AFB);
            for (int i = tid; i < 192 * 36; i += 256) {
                const int m = i / 36, p = i % 36;
                unsigned h = 0, l = 0;
                if (p < 32) bsplit2(afp[m * 68 + 2 * p], afp[m * 68 + 2 * p + 1], h, l);
                *(unsigned*)(psm + PAH + m * PAST + p * 4) = h;
                *(unsigned*)(psm + PAL + m * PAST + p * 4) = l;
            }
            for (int i = tid; i < 64 * 36; i += 256) {
                const int bb = i / 36, p = i % 36;
                unsigned h = 0, l = 0;
                if (p < 32) bsplit2(xfp[bb * 68 + 2 * p], xfp[bb * 68 + 2 * p + 1], h, l);
                *(unsigned*)(psm + PXH + bb * PAST + p * 4) = h;
                *(unsigned*)(psm + PXL + bb * PAST + p * 4) = l;
            }
        }
        __syncthreads();
        if (c + 2 < nchunks) stage(c + 2, b);

        // ---- MMA: 3 combos per k16 ----
        const unsigned abhi = sb + PAH + ms * (48 * PAST);
        const unsigned ablo = sb + PAL + ms * (48 * PAST);
        const unsigned xh   = sb + PXH + nh * 64;
        const unsigned xl   = sb + PXL + nh * 64;
        #pragma unroll
        for (int k16 = 0; k16 < 4; k16++) {
            const unsigned arow = (lane & 15) * PAST + (lane >> 4) * 16 + k16 * 32;
            unsigned ahi[3][4], alo[3][4];
            LDSM4(ahi[0], abhi + arow);
            LDSM4(ahi[1], abhi + arow + 16 * PAST);
            LDSM4(ahi[2], abhi + arow + 32 * PAST);
            LDSM4(alo[0], ablo + arow);
            LDSM4(alo[1], ablo + arow + 16 * PAST);
            LDSM4(alo[2], ablo + arow + 32 * PAST);
            const unsigned xrow = (unsigned)((k16 * 16 + (lane & 15)) * PAST)
                                + (lane >> 4) * 16;
            unsigned bh[2][4], bl[2][4];
            #pragma unroll
            for (int g = 0; g < 2; g++) LDSM4T(bh[g], xh + xrow + g * 32);
            #pragma unroll
            for (int g = 0; g < 2; g++) LDSM4T(bl[g], xl + xrow + g * 32);
            #pragma unroll
            for (int t = 0; t < 3; t++) {
                #pragma unroll
                for (int g = 0; g < 2; g++) {
                    mma16816(acc[t][2 * g],     ahi[t], bh[g][0], bh[g][1]);
                    mma16816(acc[t][2 * g + 1], ahi[t], bh[g][2], bh[g][3]);
                    mma16816(acc[t][2 * g],     alo[t], bh[g][0], bh[g][1]);
                    mma16816(acc[t][2 * g + 1], alo[t], bh[g][2], bh[g][3]);
                    mma16816(acc[t][2 * g],     ahi[t], bl[g][0], bl[g][1]);
                    mma16816(acc[t][2 * g + 1], ahi[t], bl[g][2], bl[g][3]);
                }
            }
        }
    }

    float* P = half ? g_P1 : g_P0;
    #pragma unroll
    for (int t = 0; t < 3; t++)
        #pragma unroll
        for (int nn = 0; nn < 4; nn++) {
            const int m = ms * 48 + t * 16 + (lane >> 2);
            const int n = n0 + nh * 32 + nn * 8 + 2 * (lane & 3);
            P[m * 4096 + n]           = acc[t][nn][0];
            P[m * 4096 + n + 1]       = acc[t][nn][1];
            P[(m + 8) * 4096 + n]     = acc[t][nn][2];
            P[(m + 8) * 4096 + n + 1] = acc[t][nn][3];
        }
}

// ---------------------------------------------------------------------------
// Repack: combine P partials -> W bf16 hi/lo tiles [32 kc][192 m][72 kpad].
// A[m][n] = P[m][n] - P[m+96][2048+n];  B[k][n] = P[k][2048+n] + P[k+96][n].
// ---------------------------------------------------------------------------
__global__ void __launch_bounds__(256) cqt_repack() {
    const int i = blockIdx.x * 256 + threadIdx.x;
    if (i >= WELEMS) return;
    const int kc = i / (192 * 72);
    const int r  = i % (192 * 72);
    const int m  = r / 72;
    const int kp = r % 72;
    float v = 0.f;
    if (kp < 64) {
        const int n = kc * 64 + kp;
        if (m < NBINS) {
            v = (g_P0[m * 4096 + n] + g_P1[m * 4096 + n])
              - (g_P0[(m + 96) * 4096 + 2048 + n] + g_P1[(m + 96) * 4096 + 2048 + n]);
        } else if (m >= 96 && m < 96 + NBINS) {
            const int k = m - 96;
            v = (g_P0[k * 4096 + 2048 + n] + g_P1[k * 4096 + 2048 + n])
              + (g_P0[m * 4096 + n] + g_P1[m * 4096 + n]);
        }
    }
    const __nv_bfloat16 h = __float2bfloat16(v);
    d_Whi[i] = h;
    d_Wlo[i] = __float2bfloat16(v - __bfloat162float(h));
}

// ---------------------------------------------------------------------------
// Main HMMA GEMM with in-kernel x convert (unchanged).
// ---------------------------------------------------------------------------
#define AST    144
#define ABYTES (192 * 144)
#define XFST   272
#define XF32B  (128 * XFST)
#define STG    (2 * ABYTES + XF32B)
#define XTST   272
#define XTILE  (64 * XTST)
#define XH_OFF 0
#define XL_OFF XTILE
#define STG0   (2 * XTILE)
#define SMEM_MAIN (STG0 + 2 * STG)

__global__ void __launch_bounds__(256, 1) cqt_mma(const float* __restrict__ x,
                                                  float* __restrict__ out) {
    extern __shared__ __align__(128) char dsm[];
    const unsigned sb = smem_u32(dsm);
    const int tid  = threadIdx.x;
    const int lane = tid & 31;
    const int wid  = tid >> 5;
    const int ms   = wid >> 1;
    const int nh   = wid & 1;
    const int f0   = blockIdx.x * 128;

    float acc[3][8][4];
    #pragma unroll
    for (int t = 0; t < 3; t++)
        #pragma unroll
        for (int nn = 0; nn < 8; nn++)
            #pragma unroll
            for (int j = 0; j < 4; j++) acc[t][nn][j] = 0.f;

    auto stage = [&](int kc, int b) {
        const unsigned sbuf = sb + STG0 + b * STG;
        const char* whi = (const char*)d_Whi + (size_t)kc * ABYTES;
        const char* wlo = (const char*)d_Wlo + (size_t)kc * ABYTES;
        for (int i = tid; i < ABYTES / 16; i += 256) {
            CPA(sbuf + i * 16, whi + i * 16);
            CPA(sbuf + ABYTES + i * 16, wlo + i * 16);
        }
        const unsigned xf = sbuf + 2 * ABYTES;
        for (int i = tid; i < 2048; i += 256) {
            const int f = i >> 4, seg = i & 15;
            const long gi = (long)(f0 + f) * HOP + kc * 64 + seg * 4;
            const long rem = (long)T_SAMPLES - gi;
            const int nb = rem >= 4 ? 16 : (rem > 0 ? (int)rem * 4 : 0);
            CPA_Z(xf + f * XFST + seg * 16, x + gi, nb);
        }
        CPCOMMIT();
    };

    stage(0, 0);
    stage(1, 1);

    for (int kc = 0; kc < 32; kc++) {
        const int b = kc & 1;
        CPWAIT1();
        __syncthreads();

        {
            const float* xfp = (const float*)(dsm + STG0 + b * STG + 2 * ABYTES);
            const int kk  = tid & 63;
            const int oct = tid >> 6;
            #pragma unroll
            for (int g = 0; g < 4; g++) {
                unsigned h[4], l[4];
                #pragma unroll
                for (int p = 0; p < 4; p++) {
                    const int f = oct * 32 + g * 8 + p * 2;
                    bsplit2(xfp[f * 68 + kk], xfp[(f + 1) * 68 + kk], h[p], l[p]);
                }
                const int fo = oct * 32 + g * 8;
                *(uint4*)(dsm + XH_OFF + kk * XTST + fo * 2) =
                    make_uint4(h[0], h[1], h[2], h[3]);
                *(uint4*)(dsm + XL_OFF + kk * XTST + fo * 2) =
                    make_uint4(l[0], l[1], l[2], l[3]);
            }
        }
        __syncthreads();

        const unsigned abhi = sb + STG0 + b * STG + ms * (48 * AST);
        const unsigned ablo = abhi + ABYTES;
        const unsigned xh = sb + XH_OFF + nh * 128;
        const unsigned xl = sb + XL_OFF + nh * 128;
        #pragma unroll
        for (int k16 = 0; k16 < 4; k16++) {
            const unsigned arow = (lane & 15) * AST + (lane >> 4) * 16 + k16 * 32;
            unsigned ahi[3][4], alo[3][4];
            LDSM4(ahi[0], abhi + arow);
            LDSM4(ahi[1], abhi + arow + 16 * AST);
            LDSM4(ahi[2], abhi + arow + 32 * AST);
            LDSM4(alo[0], ablo + arow);
            LDSM4(alo[1], ablo + arow + 16 * AST);
            LDSM4(alo[2], ablo + arow + 32 * AST);
            const unsigned xrow = (unsigned)((k16 * 16 + (lane & 15)) * XTST)
                                + (lane >> 4) * 16;
            unsigned bh[4][4], bl[4][4];
            #pragma unroll
            for (int g = 0; g < 4; g++) LDSM4T(bh[g], xh + xrow + g * 32);
            #pragma unroll
            for (int g = 0; g < 4; g++) LDSM4T(bl[g], xl + xrow + g * 32);
            #pragma unroll
            for (int t = 0; t < 3; t++) {
                #pragma unroll
                for (int g = 0; g < 4; g++) {
                    mma16816(acc[t][2 * g],     ahi[t], bh[g][0], bh[g][1]);
                    mma16816(acc[t][2 * g + 1], ahi[t], bh[g][2], bh[g][3]);
                    mma16816(acc[t][2 * g],     alo[t], bh[g][0], bh[g][1]);
                    mma16816(acc[t][2 * g + 1], alo[t], bh[g][2], bh[g][3]);
                    mma16816(acc[t][2 * g],     ahi[t], bl[g][0], bl[g][1]);
                    mma16816(acc[t][2 * g + 1], ahi[t], bl[g][2], bl[g][3]);
                }
            }
        }
        __syncthreads();
        if (kc + 2 < 32) stage(kc + 2, b);
    }

    __syncthreads();
    float* sI = (float*)dsm;
    if (ms >= 2) {
        #pragma unroll
        for (int t = 0; t < 3; t++)
            #pragma unroll
            for (int nn = 0; nn < 8; nn++) {
                const int mi = (ms - 2) * 48 + t * 16 + (lane >> 2);
                const int nl = nh * 64 + nn * 8 + 2 * (lane & 3);
                sI[mi * 132 + nl]           = acc[t][nn][0];
                sI[mi * 132 + nl + 1]       = acc[t][nn][1];
                sI[(mi + 8) * 132 + nl]     = acc[t][nn][2];
                sI[(mi + 8) * 132 + nl + 1] = acc[t][nn][3];
            }
    }
    __syncthreads();
    if (ms < 2) {
        #pragma unroll
        for (int t = 0; t < 3; t++)
            #pragma unroll
            for (int nn = 0; nn < 8; nn++) {
                const int m0 = ms * 48 + t * 16 + (lane >> 2);
                const int nl = nh * 64 + nn * 8 + 2 * (lane & 3);
                const int f  = f0 + nl;
                #pragma unroll
                for (int half = 0; half < 2; half++) {
                    const int m = m0 + half * 8;
                    if (m < NBINS) {
                        const float r0 = acc[t][nn][half * 2];
                        const float r1 = acc[t][nn][half * 2 + 1];
                        const float i0 = sI[m * 132 + nl];
                        const float i1 = sI[m * 132 + nl + 1];
                        if (f < NFRAMES)
                            out[m * NFRAMES + f] = sqrtf(r0 * r0 + i0 * i0);
                        if (f + 1 < NFRAMES)
                            out[m * NFRAMES + f + 1] = sqrtf(r1 * r1 + i1 * i1);
                    }
                }
            }
    }
}

extern "C" void kernel_launch(void* const* d_in, const int* in_sizes, int n_in,
                              void* d_out, int out_size) {
    const float* x    = (const float*)d_in[0];
    const float* wcos = (const float*)d_in[1];
    const float* wsin = (const float*)d_in[2];
    const float* kr   = (const float*)d_in[3];
    const float* ki   = (const float*)d_in[4];
    float* out = (float*)d_out;

    cudaFuncSetAttribute(cqt_pgemm, cudaFuncAttributeMaxDynamicSharedMemorySize,
                         SMEM_PG);
    cudaFuncSetAttribute(cqt_mma, cudaFuncAttributeMaxDynamicSharedMemorySize,
                         SMEM_MAIN);

    cqt_pgemm<<<dim3(64, 2), 256, SMEM_PG>>>(wcos, wsin, kr, ki);
    cqt_repack<<<(WELEMS + 255) / 256, 256>>>();
    cqt_mma<<<128, 256, SMEM_MAIN>>>(x, out);
}